// round 16
// baseline (speedup 1.0000x reference)
#include <cuda_runtime.h>

#define NN 8
#define LL 6400
#define KK 100
#define CC 256
#define L2DIM (2*LL)
#define NCHUNK 25          // mask chunks of 256 l per n
#define NWORDS (NCHUNK*8)  // 200 ballot words per n
#define RCH 64             // reduce chunks per n (200 rows each)

#define GDC_LAUNCH() asm volatile("griddepcontrol.launch_dependents;" ::: "memory")
#define GDC_WAIT()   asm volatile("griddepcontrol.wait;" ::: "memory")

// Scratch (no allocations allowed) — fully rewritten every launch.
__device__ float    d_partT[NN][KK][RCH]; // transposed partials
__device__ int      d_ind[NN];            // argmax index per n
__device__ unsigned d_bits[NN][NWORDS];   // selection bitmask, 32 l per word
__device__ int      d_srcrow[NN][LL];     // inverse perm: dst rank -> src row
__device__ int      d_len[NN];
__device__ int      d_rctr[NN];           // reduce ticket; reset in-kernel
__device__ int      d_ticket[NN];         // mask ticket;   reset in-kernel

// ------------------- column partial sums + (elected) argmax -------------------
// grid (RCH, NN), block 256 (250 active). Chunk = 200 rows = 5000 float4
// streamed fully contiguously (4*250 = 1000 ≡ 0 mod 100 -> column phase
// 4*(t%25) loop-invariant, rows advance 10/iter). The LAST ticket block per n
// computes argmax_k S0[k]*S1[k] once into d_ind[n] (L2-resident read).
__global__ void tf_reduce_kernel(const float* __restrict__ prob) {
    int n = blockIdx.y;
    int chunk = blockIdx.x;
    int t = threadIdx.x;
    const float4* base = (const float4*)(prob + ((size_t)n * L2DIM + (size_t)chunk * 200) * KK);

    __shared__ float4 s[250];
    __shared__ float  bv[128];
    __shared__ int    bi[128];
    __shared__ int    s_tick;

    float4 acc = make_float4(0.f, 0.f, 0.f, 0.f);
    if (t < 250) {
        #pragma unroll
        for (int it = 0; it < 20; it++) {
            float4 v = __ldcs(base + t + it * 250);   // streaming: read-once
            acc.x += v.x; acc.y += v.y; acc.z += v.z; acc.w += v.w;
        }
        s[t] = acc;
    }
    __syncthreads();
    if (t < 25) {
        float4 a = s[t];
        #pragma unroll
        for (int g = 1; g < 10; g++) {
            float4 v = s[t + 25 * g];
            a.x += v.x; a.y += v.y; a.z += v.z; a.w += v.w;
        }
        int k = 4 * t;
        d_partT[n][k    ][chunk] = a.x;
        d_partT[n][k + 1][chunk] = a.y;
        d_partT[n][k + 2][chunk] = a.z;
        d_partT[n][k + 3][chunk] = a.w;
    }
    __syncthreads();
    __threadfence();                       // release partT
    if (t == 0) s_tick = atomicAdd(&d_rctr[n], 1);
    __syncthreads();

    if (s_tick == RCH - 1) {               // elected: compute argmax once
        __threadfence();                   // acquire all partT for this n
        // argmax_k S0[k]*S1[k]; top_k tie-break = lowest index first.
        if (t < 128) {
            float best = -1.0f; int bidx = KK;
            if (t < KK) {
                const float4* p = (const float4*)&d_partT[n][t][0];  // 64 floats
                float s0 = 0.f, s1 = 0.f;
                #pragma unroll
                for (int c = 0; c < 8; c++) {       // chunks 0..31 = half 0
                    float4 v = __ldcg(p + c);
                    s0 += (v.x + v.y) + (v.z + v.w);
                }
                #pragma unroll
                for (int c = 8; c < 16; c++) {      // chunks 32..63 = half 1
                    float4 v = __ldcg(p + c);
                    s1 += (v.x + v.y) + (v.z + v.w);
                }
                best = s0 * s1; bidx = t;
            }
            bv[t] = best; bi[t] = bidx;
        }
        __syncthreads();
        for (int st = 64; st > 0; st >>= 1) {
            if (t < st) {
                if (bv[t+st] > bv[t] || (bv[t+st] == bv[t] && bi[t+st] < bi[t])) {
                    bv[t] = bv[t+st]; bi[t] = bi[t+st];
                }
            }
            __syncthreads();
        }
        if (t == 0) { d_ind[n] = bi[0]; d_rctr[n] = 0; }  // reset for replay
    }
    GDC_LAUNCH();    // PDL: dependents see all primary writes at wait-release
}

// ---------------- ballot + (last block) scan/perm/mask -----------------------
// grid (NCHUNK, NN), block 256. Reads precomputed d_ind[n]; ballots the
// selection mask; last block per n (ticket) does word scan, inverse perm,
// d_len, and the (n, 6400) output mask.
__global__ void tf_maskargmax_kernel(const float* __restrict__ topics,
                                     float* __restrict__ out_mask) {
    int n = blockIdx.y;
    int t = threadIdx.x;
    __shared__ int s_ind;
    __shared__ int s_last;

    GDC_WAIT();                    // d_ind + partT complete + visible

    if (t == 0) s_ind = d_ind[n];
    __syncthreads();

    int l = blockIdx.x * 256 + t;
    float v = __ldcs(topics + ((size_t)n * L2DIM + l) * KK + s_ind);
    unsigned ballot = __ballot_sync(0xFFFFFFFFu, v > 0.5f);
    if ((t & 31) == 0) d_bits[n][blockIdx.x * 8 + (t >> 5)] = ballot;

    // ---- last-block election (release: fence before ticket) ----
    __threadfence();
    if (t == 0) s_last = atomicAdd(&d_ticket[n], 1);
    __syncthreads();
    if (s_last != NCHUNK - 1) { GDC_LAUNCH(); return; }
    __threadfence();               // acquire: all blocks' d_bits now visible

    // word-popcount exclusive scan over 200 words
    __shared__ int ps[256];
    unsigned word = (t < NWORDS) ? d_bits[n][t] : 0u;
    int p = __popc(word);
    ps[t] = p;
    __syncthreads();
    for (int off = 1; off < 256; off <<= 1) {
        int x = (t >= off) ? ps[t - off] : 0;
        __syncthreads();
        ps[t] += x;
        __syncthreads();
    }
    int tot = ps[NWORDS - 1];
    if (t == 0) { d_len[n] = tot; d_ticket[n] = 0; }   // reset for graph replay

    // inverse permutation: emit src row index for each set bit
    if (t < NWORDS) {
        int off = ps[t] - p;
        unsigned w = word;
        int base = t * 32;
        while (w) {
            int b = __ffs(w) - 1;
            d_srcrow[n][off++] = base + b;
            w &= w - 1;
        }
    }

    float* m = out_mask + (size_t)n * LL;
    #pragma unroll
    for (int i = t; i < LL; i += 256) m[i] = (i < tot) ? 1.0f : 0.0f;
    GDC_LAUNCH();
}

// -------------------------------------------- gather compact + zero-fill
// grid (LL/8, NN), block (64,4). Each thread handles 2 independent dst rows
// (ty and ty+4) -> 2 in-flight loads, perfectly sequential streaming writes.
__global__ void tf_gather_kernel(const float* __restrict__ feat,
                                 float* __restrict__ out) {
    int n = blockIdx.y;
    int t = threadIdx.x;            // 64 lanes = one 1KB row
    int l1 = blockIdx.x * 8 + threadIdx.y;
    int l2 = l1 + 4;
    const float* fsrc = feat + (size_t)n * LL * CC;
    float*       dst  = out  + (size_t)n * LL * CC;

    GDC_WAIT();                     // perm + len now complete + visible

    int len = d_len[n];
    bool v1 = l1 < len, v2 = l2 < len;
    int s1 = v1 ? d_srcrow[n][l1] : 0;     // L2-resident broadcast
    int s2 = v2 ? d_srcrow[n][l2] : 0;

    float4 a = make_float4(0.f, 0.f, 0.f, 0.f);
    float4 b = a;
    if (v1) a = __ldcs((const float4*)(fsrc + (size_t)s1 * CC) + t);
    if (v2) b = __ldcs((const float4*)(fsrc + (size_t)s2 * CC) + t);

    ((float4*)(dst + (size_t)l1 * CC))[t] = a;
    ((float4*)(dst + (size_t)l2 * CC))[t] = b;
}

extern "C" void kernel_launch(void* const* d_in, const int* in_sizes, int n_in,
                              void* d_out, int out_size) {
    const float* feat   = (const float*)d_in[0];   // (8, 6400, 256)
    const float* prob   = (const float*)d_in[1];   // (8, 12800, 100)
    const float* topics = (const float*)d_in[2];   // (8, 12800, 100)
    // d_in[3] = n_samples: only top-1 index is consumed -> argmax; unused here.

    float* out_feat = (float*)d_out;               // (8, 6400, 256)
    float* out_mask = out_feat + (size_t)NN*LL*CC; // (8, 6400)

    tf_reduce_kernel<<<dim3(RCH, NN), 256>>>(prob);

    cudaLaunchAttribute attr[1];
    attr[0].id = cudaLaunchAttributeProgrammaticStreamSerialization;
    attr[0].val.programmaticStreamSerializationAllowed = 1;

    {
        cudaLaunchConfig_t cfg = {};
        cfg.gridDim  = dim3(NCHUNK, NN);
        cfg.blockDim = dim3(256);
        cfg.stream   = 0;
        cfg.attrs    = attr;
        cfg.numAttrs = 1;
        cudaLaunchKernelEx(&cfg, tf_maskargmax_kernel, topics, out_mask);
    }
    {
        cudaLaunchConfig_t cfg = {};
        cfg.gridDim  = dim3(LL/8, NN);
        cfg.blockDim = dim3(64, 4);
        cfg.stream   = 0;
        cfg.attrs    = attr;
        cfg.numAttrs = 1;
        cudaLaunchKernelEx(&cfg, tf_gather_kernel, feat, out_feat);
    }
}